// round 1
// baseline (speedup 1.0000x reference)
#include <cuda_runtime.h>
#include <cuda_bf16.h>
#include <cstdint>

// Problem constants
#define CH 512
#define TT 4096
#define BB 2
#define KS 12
#define NN 10

// Scratch (device globals; no allocation allowed)
__device__ float  g_c[BB * CH * TT];      // c = W @ feat_context + bias, [B, C, T]
__device__ float  g_band[BB * KS * TT];   // band[b][k][s] = cont[b, s+k, s]
__device__ float  g_rows[BB * NN * TT];   // rows[b][r][s] = cont[b, r, s]
__device__ double g_total;

// ---------------------------------------------------------------------------
// Kernel 1: SGEMM  c[b,d,t] = sum_c W[d,c] * fc[b,c,t] + bias[d]
// Tiles: BM=64 x BN=64, BK=16, 128 threads, each computes 8x4 outputs.
// ---------------------------------------------------------------------------
#define BM 64
#define BN 64
#define BKK 16

__global__ __launch_bounds__(128) void gemm_k(const float* __restrict__ W,
                                              const float* __restrict__ bias,
                                              const float* __restrict__ fc) {
    __shared__ float As[BKK][BM];       // A transposed: As[k][m]
    __shared__ float Bs[BKK][BN];

    const int b   = blockIdx.z;
    const int t0  = blockIdx.x * BN;
    const int d0  = blockIdx.y * BM;
    const int tid = threadIdx.x;
    const int rg  = tid >> 4;    // 0..7   -> row group
    const int cg  = tid & 15;    // 0..15  -> col group
    const int tm0 = rg * 8;
    const int tn0 = cg * 4;

    float acc[8][4];
#pragma unroll
    for (int i = 0; i < 8; i++)
#pragma unroll
        for (int j = 0; j < 4; j++) acc[i][j] = 0.f;

    const float* fcb = fc + (size_t)b * CH * TT;

    for (int k0 = 0; k0 < CH; k0 += BKK) {
        // Load A tile (64 x 16) as float4, store transposed
#pragma unroll
        for (int i = 0; i < 2; i++) {
            int v   = tid + i * 128;          // 0..255
            int row = v >> 2;                 // 0..63
            int c4  = (v & 3) * 4;            // 0,4,8,12
            float4 a = *(const float4*)(W + (size_t)(d0 + row) * CH + k0 + c4);
            As[c4 + 0][row] = a.x;
            As[c4 + 1][row] = a.y;
            As[c4 + 2][row] = a.z;
            As[c4 + 3][row] = a.w;
        }
        // Load B tile (16 x 64) as float4
#pragma unroll
        for (int i = 0; i < 2; i++) {
            int v   = tid + i * 128;          // 0..255
            int row = v >> 4;                 // 0..15
            int c4  = (v & 15) * 4;           // 0..60
            *(float4*)(&Bs[row][c4]) =
                *(const float4*)(fcb + (size_t)(k0 + row) * TT + t0 + c4);
        }
        __syncthreads();

#pragma unroll
        for (int kk = 0; kk < BKK; kk++) {
            float4 a0 = *(const float4*)(&As[kk][tm0]);
            float4 a1 = *(const float4*)(&As[kk][tm0 + 4]);
            float4 bf = *(const float4*)(&Bs[kk][tn0]);
            float av[8] = {a0.x, a0.y, a0.z, a0.w, a1.x, a1.y, a1.z, a1.w};
            float bv[4] = {bf.x, bf.y, bf.z, bf.w};
#pragma unroll
            for (int i = 0; i < 8; i++)
#pragma unroll
                for (int j = 0; j < 4; j++) acc[i][j] += av[i] * bv[j];
        }
        __syncthreads();
    }

    float* outb = g_c + (size_t)b * CH * TT;
#pragma unroll
    for (int i = 0; i < 8; i++) {
        float bi = bias[d0 + tm0 + i];
        float4 o;
        o.x = acc[i][0] + bi;
        o.y = acc[i][1] + bi;
        o.z = acc[i][2] + bi;
        o.w = acc[i][3] + bi;
        *(float4*)(&outb[(size_t)(d0 + tm0 + i) * TT + t0 + tn0]) = o;
    }
}

// ---------------------------------------------------------------------------
// Kernel 2: band + rows
//   band[b,k,s] = sum_c fe[b,c,s+k] * c[b,c,s]   (k < 12)
//   rows[b,r,s] = sum_c fe[b,c,r]   * c[b,c,s]   (r < 10)
// One thread per s; C streamed through smem in chunks of 16.
// ---------------------------------------------------------------------------
#define TS 128
#define CCH 16

__global__ __launch_bounds__(TS) void bandrow_k(const float* __restrict__ fe) {
    __shared__ float c_sm[CCH][TS];
    __shared__ float fe_sm[CCH][TS + KS];   // columns s0 .. s0+TS+11
    __shared__ float fer_sm[CCH][NN];       // fe columns 0..9

    const int b   = blockIdx.y;
    const int s0  = blockIdx.x * TS;
    const int tid = threadIdx.x;
    const int s   = s0 + tid;

    float acc[KS];
    float accr[NN];
#pragma unroll
    for (int k = 0; k < KS; k++) acc[k] = 0.f;
#pragma unroll
    for (int r = 0; r < NN; r++) accr[r] = 0.f;

    const float* feb = fe + (size_t)b * CH * TT;
    const float* cb  = g_c + (size_t)b * CH * TT;

    for (int c0 = 0; c0 < CH; c0 += CCH) {
        for (int i = tid; i < CCH * TS; i += TS) {
            int cc = i / TS, j = i % TS;
            c_sm[cc][j] = cb[(size_t)(c0 + cc) * TT + s0 + j];
        }
        for (int i = tid; i < CCH * (TS + KS); i += TS) {
            int cc = i / (TS + KS), j = i % (TS + KS);
            int col = s0 + j;
            fe_sm[cc][j] = (col < TT) ? feb[(size_t)(c0 + cc) * TT + col] : 0.f;
        }
        for (int i = tid; i < CCH * NN; i += TS) {
            int cc = i / NN, r = i % NN;
            fer_sm[cc][r] = feb[(size_t)(c0 + cc) * TT + r];
        }
        __syncthreads();

#pragma unroll
        for (int cc = 0; cc < CCH; cc++) {
            float cv = c_sm[cc][tid];
#pragma unroll
            for (int k = 0; k < KS; k++) acc[k] += fe_sm[cc][tid + k] * cv;
#pragma unroll
            for (int r = 0; r < NN; r++) accr[r] += fer_sm[cc][r] * cv;
        }
        __syncthreads();
    }

#pragma unroll
    for (int k = 0; k < KS; k++)
        g_band[((size_t)b * KS + k) * TT + s] = acc[k];
#pragma unroll
    for (int r = 0; r < NN; r++)
        g_rows[((size_t)b * NN + r) * TT + s] = accr[r];
}

// ---------------------------------------------------------------------------
// Kernel 3: loss reduction (fp64 accumulation)
//   total = sum_{b,k,s<T-k} logsig(band[b,k,s])
//         + NUM_NEG * sum_{k,b,r,s} logsig(-rows[b, r, neg_idx[k,s,r]])
// ---------------------------------------------------------------------------
__device__ __forceinline__ float logsigf(float x) {
    // min(x,0) - log1p(exp(-|x|))  (stable, matches jax.nn.log_sigmoid)
    return fminf(x, 0.f) - log1pf(expf(-fabsf(x)));
}

__global__ void zero_k() { g_total = 0.0; }

__global__ void loss_k(const int* __restrict__ neg_idx) {
    const int gid    = blockIdx.x * blockDim.x + threadIdx.x;
    const int stride = gridDim.x * blockDim.x;
    double local = 0.0;

    // positives: band, masked to s + k < T
    const int N1 = BB * KS * TT;
    for (int i = gid; i < N1; i += stride) {
        int s = i % TT;
        int k = (i / TT) % KS;
        if (s + k < TT) local += (double)logsigf(g_band[i]);
    }

    // negatives: i = ((k*BB + b)*TT + s)*NN + r  (r fastest -> coalesced neg_idx)
    const int N2 = KS * BB * TT * NN;
    for (int i = gid; i < N2; i += stride) {
        int r  = i % NN;
        int s  = (i / NN) % TT;
        int bk = i / (NN * TT);
        int b  = bk % BB;
        int k  = bk / BB;
        int idx = neg_idx[(k * TT + s) * NN + r];
        float v = g_rows[((size_t)b * NN + r) * TT + idx];
        local += (double)NN * (double)logsigf(-v);
    }

    // in-block reduction
#pragma unroll
    for (int off = 16; off; off >>= 1)
        local += __shfl_down_sync(0xffffffffu, local, off);
    __shared__ double warp_sums[32];
    int lane = threadIdx.x & 31, wid = threadIdx.x >> 5;
    if (lane == 0) warp_sums[wid] = local;
    __syncthreads();
    if (wid == 0) {
        int nw = blockDim.x >> 5;
        local = (lane < nw) ? warp_sums[lane] : 0.0;
#pragma unroll
        for (int off = 16; off; off >>= 1)
            local += __shfl_down_sync(0xffffffffu, local, off);
        if (lane == 0) atomicAdd(&g_total, local);
    }
}

__global__ void write_k(float* __restrict__ out) { out[0] = (float)g_total; }

// ---------------------------------------------------------------------------
// Launch
// ---------------------------------------------------------------------------
extern "C" void kernel_launch(void* const* d_in, const int* in_sizes, int n_in,
                              void* d_out, int out_size) {
    const float* fe   = (const float*)d_in[0];  // feat_enc     [B,C,T]
    const float* fc   = (const float*)d_in[1];  // feat_context [B,C,T]
    const float* W    = (const float*)d_in[2];  // [C,C]
    const float* bias = (const float*)d_in[3];  // [C]
    const int*   neg  = (const int*)d_in[4];    // [K_STEPS,T,NUM_NEG]

    dim3 gg(TT / BN, CH / BM, BB);
    gemm_k<<<gg, 128>>>(W, bias, fc);

    dim3 gb(TT / TS, BB);
    bandrow_k<<<gb, TS>>>(fe);

    zero_k<<<1, 1>>>();
    loss_k<<<512, 256>>>(neg);
    write_k<<<1, 1>>>((float*)d_out);
}

// round 3
// speedup vs baseline: 3.9698x; 3.9698x over previous
#include <cuda_runtime.h>
#include <cuda_bf16.h>
#include <cstdint>

// Problem constants
#define CH 512
#define TT 4096
#define BB 2
#define KS 12
#define NN 10
#define QSPLIT 8

// ---------------------------------------------------------------------------
// Scratch (device globals; allocation is forbidden)
// ---------------------------------------------------------------------------
__device__ __nv_bfloat16 g_Wb[CH * CH];            // W in bf16, row-major [d][e]
__device__ __nv_bfloat16 g_cb[BB * CH * TT];       // c = W@fc + b, bf16 [B,C,T]
__device__ float  g_band_p[QSPLIT * BB * KS * TT];
__device__ float  g_rows_p[QSPLIT * BB * NN * TT];
__device__ float  g_band[BB * KS * TT];
__device__ float  g_rows[BB * NN * TT];
__device__ double g_total;

// ---------------------------------------------------------------------------
// PTX helpers (baseline sm_80+ instructions only: ldmatrix + mma.sync)
// ---------------------------------------------------------------------------
__device__ __forceinline__ uint32_t smem_u32(const void* p) {
    uint32_t a;
    asm("{ .reg .u64 t; cvta.to.shared.u64 t, %1; cvt.u32.u64 %0, t; }"
        : "=r"(a) : "l"(p));
    return a;
}

__device__ __forceinline__ void ldsm_x4(uint32_t* r, uint32_t addr) {
    asm volatile("ldmatrix.sync.aligned.m8n8.x4.shared.b16 {%0,%1,%2,%3}, [%4];"
                 : "=r"(r[0]), "=r"(r[1]), "=r"(r[2]), "=r"(r[3]) : "r"(addr));
}
__device__ __forceinline__ void ldsm_x4_t(uint32_t* r, uint32_t addr) {
    asm volatile("ldmatrix.sync.aligned.m8n8.x4.trans.shared.b16 {%0,%1,%2,%3}, [%4];"
                 : "=r"(r[0]), "=r"(r[1]), "=r"(r[2]), "=r"(r[3]) : "r"(addr));
}
__device__ __forceinline__ void mma16816(float* d, const uint32_t* a,
                                         const uint32_t* b) {
    asm volatile(
        "mma.sync.aligned.m16n8k16.row.col.f32.bf16.bf16.f32 "
        "{%0,%1,%2,%3}, {%4,%5,%6,%7}, {%8,%9}, {%0,%1,%2,%3};"
        : "+f"(d[0]), "+f"(d[1]), "+f"(d[2]), "+f"(d[3])
        : "r"(a[0]), "r"(a[1]), "r"(a[2]), "r"(a[3]), "r"(b[0]), "r"(b[1]));
}

// ---------------------------------------------------------------------------
// Kernel A: convert W to bf16
// ---------------------------------------------------------------------------
__global__ void convw_k(const float* __restrict__ W) {
    int i = blockIdx.x * blockDim.x + threadIdx.x;   // over float2
    if (i < CH * CH / 2) {
        float2 v = ((const float2*)W)[i];
        ((__nv_bfloat162*)g_Wb)[i] = __floats2bfloat162_rn(v.x, v.y);
    }
}

// ---------------------------------------------------------------------------
// Kernel B: bf16 tensor-core GEMM via mma.sync
//   c[b,d,t] = sum_e W[d,e] * fc[b,e,t] + bias[d], output bf16 to g_cb.
// Block 128(m) x 128(n), BK=32, 256 threads = 8 warps (2m x 4n),
// warp tile 64(m) x 32(n) = 4 m-frags x 4 n-frags of m16n8k16.
// A smem: [128][32] bf16 rows padded to 40 elems (80 B).
// B smem: [32][128] bf16 rows padded to 136 elems (272 B), ldmatrix.trans.
// ---------------------------------------------------------------------------
#define BM 128
#define BN 128
#define BKT 32
#define APAD 40     // elems per A row
#define BPAD 136    // elems per B row

__global__ __launch_bounds__(256) void gemm_k(const float* __restrict__ fc,
                                              const float* __restrict__ bias) {
    __shared__ __nv_bfloat16 As[BM * APAD];
    __shared__ __nv_bfloat16 Bs[BKT * BPAD];

    const int tid  = threadIdx.x;
    const int lane = tid & 31;
    const int wid  = tid >> 5;
    const int wm   = wid >> 2;          // 0..1
    const int wn   = wid & 3;           // 0..3

    const int b  = blockIdx.z;
    const int t0 = blockIdx.x * BN;
    const int d0 = blockIdx.y * BM;

    const uint32_t as_base = smem_u32(As);
    const uint32_t bs_base = smem_u32(Bs);

    // ldmatrix lane addressing (byte offsets within tile, before kstep/frag)
    const int grp = lane >> 3, lr = lane & 7;
    // A: row = wm*64 + fm*16 + lr + (grp&1)*8 ; col = ks*16 + (grp>>1)*8
    const uint32_t a_lane = (uint32_t)((wm * 64 + lr + (grp & 1) * 8) * APAD * 2
                                       + ((grp >> 1) * 8) * 2);
    // B (trans): k-row = ks*16 + (grp&1)*8 + lr ; n-col = wn*32 + fn*16 + (grp>>1)*8
    const uint32_t b_lane = (uint32_t)(((grp & 1) * 8 + lr) * BPAD * 2
                                       + (wn * 32 + (grp >> 1) * 8) * 2);

    float acc[4][4][4];
#pragma unroll
    for (int i = 0; i < 4; i++)
#pragma unroll
        for (int j = 0; j < 4; j++)
#pragma unroll
            for (int q = 0; q < 4; q++) acc[i][j][q] = 0.f;

    const float* fcb = fc + (size_t)b * CH * TT;

    // staging registers
    uint4  areg[2];
    float4 breg[4];

    // ---- load tile 0 into regs
    {
#pragma unroll
        for (int j = 0; j < 2; j++) {
            int seg = tid + j * 256;               // 0..511
            int row = seg >> 2, c8 = seg & 3;
            areg[j] = *(const uint4*)(g_Wb + (size_t)(d0 + row) * CH + c8 * 8);
        }
#pragma unroll
        for (int j = 0; j < 4; j++) {
            int seg = tid + j * 256;               // 0..1023
            int row = seg >> 5, c4 = seg & 31;
            breg[j] = *(const float4*)(fcb + (size_t)row * TT + t0 + c4 * 4);
        }
    }

    for (int kt = 0; kt < CH / BKT; kt++) {
        __syncthreads();   // previous compute done reading smem
        // store staged regs to smem
#pragma unroll
        for (int j = 0; j < 2; j++) {
            int seg = tid + j * 256;
            int row = seg >> 2, c8 = seg & 3;
            *(uint4*)(As + row * APAD + c8 * 8) = areg[j];
        }
#pragma unroll
        for (int j = 0; j < 4; j++) {
            int seg = tid + j * 256;
            int row = seg >> 5, c4 = seg & 31;
            float4 v = breg[j];
            __nv_bfloat162* p = (__nv_bfloat162*)(Bs + row * BPAD + c4 * 4);
            p[0] = __floats2bfloat162_rn(v.x, v.y);
            p[1] = __floats2bfloat162_rn(v.z, v.w);
        }
        __syncthreads();

        // prefetch next tile
        if (kt + 1 < CH / BKT) {
            const int k0 = (kt + 1) * BKT;
#pragma unroll
            for (int j = 0; j < 2; j++) {
                int seg = tid + j * 256;
                int row = seg >> 2, c8 = seg & 3;
                areg[j] = *(const uint4*)(g_Wb + (size_t)(d0 + row) * CH + k0 + c8 * 8);
            }
#pragma unroll
            for (int j = 0; j < 4; j++) {
                int seg = tid + j * 256;
                int row = seg >> 5, c4 = seg & 31;
                breg[j] = *(const float4*)(fcb + (size_t)(k0 + row) * TT + t0 + c4 * 4);
            }
        }

        // compute: 2 k-steps of 16
#pragma unroll
        for (int ks = 0; ks < 2; ks++) {
            uint32_t af[4][4];
#pragma unroll
            for (int fm = 0; fm < 4; fm++)
                ldsm_x4(af[fm], as_base + a_lane
                                + (uint32_t)(fm * 16 * APAD * 2 + ks * 16 * 2));
            uint32_t bf[2][4];
#pragma unroll
            for (int fn = 0; fn < 2; fn++)
                ldsm_x4_t(bf[fn], bs_base + b_lane
                                  + (uint32_t)(ks * 16 * BPAD * 2 + fn * 16 * 2));
#pragma unroll
            for (int fm = 0; fm < 4; fm++)
#pragma unroll
                for (int nf = 0; nf < 4; nf++)
                    mma16816(acc[fm][nf], af[fm], &bf[nf >> 1][(nf & 1) * 2]);
        }
    }

    // ---- epilogue: add bias, convert to bf16, store
    const int rbase = lane >> 2;          // 0..7
    const int cbase = (lane & 3) * 2;     // 0,2,4,6
#pragma unroll
    for (int fm = 0; fm < 4; fm++) {
        const int d_lo = d0 + wm * 64 + fm * 16 + rbase;
        const float bi_lo = bias[d_lo];
        const float bi_hi = bias[d_lo + 8];
        __nv_bfloat16* out_lo = g_cb + ((size_t)b * CH + d_lo) * TT;
        __nv_bfloat16* out_hi = out_lo + (size_t)8 * TT;
#pragma unroll
        for (int nf = 0; nf < 4; nf++) {
            const int t = t0 + wn * 32 + nf * 8 + cbase;
            *(__nv_bfloat162*)(out_lo + t) =
                __floats2bfloat162_rn(acc[fm][nf][0] + bi_lo, acc[fm][nf][1] + bi_lo);
            *(__nv_bfloat162*)(out_hi + t) =
                __floats2bfloat162_rn(acc[fm][nf][2] + bi_hi, acc[fm][nf][3] + bi_hi);
        }
    }
}

// ---------------------------------------------------------------------------
// Kernel C: band + rows partials (C split QSPLIT ways, deterministic)
//   band[b,k,s] = sum_c fe[b,c,s+k] * c[b,c,s]
//   rows[b,r,s] = sum_c fe[b,c,r]   * c[b,c,s]
// ---------------------------------------------------------------------------
#define TS 128
#define CCH 16
#define CPQ (CH / QSPLIT)

__global__ __launch_bounds__(TS) void bandrow_k(const float* __restrict__ fe) {
    __shared__ float c_sm[CCH][TS];
    __shared__ float fe_sm[CCH][TS + KS];
    __shared__ float fer_sm[CCH][NN];

    const int b   = blockIdx.z;
    const int q   = blockIdx.y;
    const int s0  = blockIdx.x * TS;
    const int tid = threadIdx.x;
    const int s   = s0 + tid;

    float acc[KS];
    float accr[NN];
#pragma unroll
    for (int k = 0; k < KS; k++) acc[k] = 0.f;
#pragma unroll
    for (int r = 0; r < NN; r++) accr[r] = 0.f;

    const float* feb = fe + (size_t)b * CH * TT;
    const __nv_bfloat16* cb = g_cb + (size_t)b * CH * TT;

    for (int c0 = q * CPQ; c0 < (q + 1) * CPQ; c0 += CCH) {
        // c tile: bf16, vectorized bf162 loads
        for (int i = tid; i < CCH * TS / 2; i += TS) {
            int cc = i / (TS / 2), jj = (i % (TS / 2)) * 2;
            __nv_bfloat162 v =
                *(const __nv_bfloat162*)(cb + (size_t)(c0 + cc) * TT + s0 + jj);
            c_sm[cc][jj]     = __bfloat162float(v.x);
            c_sm[cc][jj + 1] = __bfloat162float(v.y);
        }
        for (int i = tid; i < CCH * (TS + KS); i += TS) {
            int cc = i / (TS + KS), j = i % (TS + KS);
            int col = s0 + j;
            fe_sm[cc][j] = (col < TT) ? feb[(size_t)(c0 + cc) * TT + col] : 0.f;
        }
        for (int i = tid; i < CCH * NN; i += TS) {
            int cc = i / NN, r = i % NN;
            fer_sm[cc][r] = feb[(size_t)(c0 + cc) * TT + r];
        }
        __syncthreads();

#pragma unroll
        for (int cc = 0; cc < CCH; cc++) {
            float cv = c_sm[cc][tid];
#pragma unroll
            for (int k = 0; k < KS; k++) acc[k] += fe_sm[cc][tid + k] * cv;
#pragma unroll
            for (int r = 0; r < NN; r++) accr[r] += fer_sm[cc][r] * cv;
        }
        __syncthreads();
    }

    const int NB = BB * KS * TT;
    const int NR = BB * NN * TT;
#pragma unroll
    for (int k = 0; k < KS; k++)
        g_band_p[q * NB + ((size_t)b * KS + k) * TT + s] = acc[k];
#pragma unroll
    for (int r = 0; r < NN; r++)
        g_rows_p[q * NR + ((size_t)b * NN + r) * TT + s] = accr[r];
}

// ---------------------------------------------------------------------------
// Kernel D: combine partials
// ---------------------------------------------------------------------------
__global__ void combine_k() {
    const int NB = BB * KS * TT;
    const int NR = BB * NN * TT;
    int i = blockIdx.x * blockDim.x + threadIdx.x;
    if (i < NB) {
        float v = 0.f;
#pragma unroll
        for (int qq = 0; qq < QSPLIT; qq++) v += g_band_p[qq * NB + i];
        g_band[i] = v;
    } else if (i < NB + NR) {
        int j = i - NB;
        float v = 0.f;
#pragma unroll
        for (int qq = 0; qq < QSPLIT; qq++) v += g_rows_p[qq * NR + j];
        g_rows[j] = v;
    }
}

// ---------------------------------------------------------------------------
// Kernel E: loss reduction (fp64 accumulation)
// ---------------------------------------------------------------------------
__device__ __forceinline__ float logsigf(float x) {
    float e = __expf(-fabsf(x));
    return fminf(x, 0.f) - __logf(1.f + e);
}

__global__ void zero_k() { g_total = 0.0; }

__global__ void loss_k(const int* __restrict__ neg_idx) {
    const int gid    = blockIdx.x * blockDim.x + threadIdx.x;
    const int stride = gridDim.x * blockDim.x;
    double local = 0.0;

    const int N1 = BB * KS * TT;
    for (int i = gid; i < N1; i += stride) {
        int s = i % TT;
        int k = (i / TT) % KS;
        if (s + k < TT) local += (double)logsigf(g_band[i]);
    }

    const int N2 = KS * BB * TT * NN;
    for (int i = gid; i < N2; i += stride) {
        int r  = i % NN;
        int s  = (i / NN) % TT;
        int bk = i / (NN * TT);
        int b  = bk % BB;
        int k  = bk / BB;
        int idx = neg_idx[(k * TT + s) * NN + r];
        float v = g_rows[((size_t)b * NN + r) * TT + idx];
        local += (double)NN * (double)logsigf(-v);
    }

#pragma unroll
    for (int off = 16; off; off >>= 1)
        local += __shfl_down_sync(0xffffffffu, local, off);
    __shared__ double warp_sums[32];
    int lane = threadIdx.x & 31, wid = threadIdx.x >> 5;
    if (lane == 0) warp_sums[wid] = local;
    __syncthreads();
    if (wid == 0) {
        int nw = blockDim.x >> 5;
        local = (lane < nw) ? warp_sums[lane] : 0.0;
#pragma unroll
        for (int off = 16; off; off >>= 1)
            local += __shfl_down_sync(0xffffffffu, local, off);
        if (lane == 0) atomicAdd(&g_total, local);
    }
}

__global__ void write_k(float* __restrict__ out) { out[0] = (float)g_total; }

// ---------------------------------------------------------------------------
// Launch
// ---------------------------------------------------------------------------
extern "C" void kernel_launch(void* const* d_in, const int* in_sizes, int n_in,
                              void* d_out, int out_size) {
    const float* fe   = (const float*)d_in[0];  // feat_enc     [B,C,T]
    const float* fc   = (const float*)d_in[1];  // feat_context [B,C,T]
    const float* W    = (const float*)d_in[2];  // [C,C]
    const float* bias = (const float*)d_in[3];  // [C]
    const int*   neg  = (const int*)d_in[4];    // [K_STEPS,T,NUM_NEG]

    convw_k<<<(CH * CH / 2 + 255) / 256, 256>>>(W);

    gemm_k<<<dim3(TT / BN, CH / BM, BB), 256>>>(fc, bias);

    bandrow_k<<<dim3(TT / TS, QSPLIT, BB), TS>>>(fe);

    const int NTOT = BB * (KS + NN) * TT;
    combine_k<<<(NTOT + 255) / 256, 256>>>();

    zero_k<<<1, 1>>>();
    loss_k<<<1024, 256>>>(neg);
    write_k<<<1, 1>>>((float*)d_out);
}

// round 5
// speedup vs baseline: 4.7045x; 1.1851x over previous
#include <cuda_runtime.h>
#include <cuda_bf16.h>
#include <cstdint>

// Problem constants
#define CH 512
#define TT 4096
#define BB 2
#define KS 12
#define NN 10
#define QS 16          // 4 m-blocks x 4 in-block channel quarters

// ---------------------------------------------------------------------------
// Scratch (device globals; allocation is forbidden)
// ---------------------------------------------------------------------------
__device__ __nv_bfloat16 g_Wb[CH * CH];          // W in bf16, row-major [d][e]
__device__ float  g_band_p[QS * BB * KS * TT];   // 6.3 MB
__device__ float  g_rows_p[QS * BB * NN * TT];   // 5.2 MB
__device__ float  g_band[BB * KS * TT];
__device__ float  g_rows[BB * NN * TT];
__device__ double g_total;

// ---------------------------------------------------------------------------
// PTX helpers (baseline sm_80+: ldmatrix + mma.sync only)
// ---------------------------------------------------------------------------
__device__ __forceinline__ uint32_t smem_u32(const void* p) {
    uint32_t a;
    asm("{ .reg .u64 t; cvta.to.shared.u64 t, %1; cvt.u32.u64 %0, t; }"
        : "=r"(a) : "l"(p));
    return a;
}
__device__ __forceinline__ void ldsm_x4(uint32_t* r, uint32_t addr) {
    asm volatile("ldmatrix.sync.aligned.m8n8.x4.shared.b16 {%0,%1,%2,%3}, [%4];"
                 : "=r"(r[0]), "=r"(r[1]), "=r"(r[2]), "=r"(r[3]) : "r"(addr));
}
__device__ __forceinline__ void ldsm_x4_t(uint32_t* r, uint32_t addr) {
    asm volatile("ldmatrix.sync.aligned.m8n8.x4.trans.shared.b16 {%0,%1,%2,%3}, [%4];"
                 : "=r"(r[0]), "=r"(r[1]), "=r"(r[2]), "=r"(r[3]) : "r"(addr));
}
__device__ __forceinline__ void mma16816(float* d, const uint32_t* a,
                                         const uint32_t* b) {
    asm volatile(
        "mma.sync.aligned.m16n8k16.row.col.f32.bf16.bf16.f32 "
        "{%0,%1,%2,%3}, {%4,%5,%6,%7}, {%8,%9}, {%0,%1,%2,%3};"
        : "+f"(d[0]), "+f"(d[1]), "+f"(d[2]), "+f"(d[3])
        : "r"(a[0]), "r"(a[1]), "r"(a[2]), "r"(a[3]), "r"(b[0]), "r"(b[1]));
}

// ---------------------------------------------------------------------------
// Kernel A: convert W to bf16
// ---------------------------------------------------------------------------
__global__ void convw_k(const float* __restrict__ W) {
    int i = blockIdx.x * blockDim.x + threadIdx.x;   // over float2
    if (i < CH * CH / 2) {
        float2 v = ((const float2*)W)[i];
        ((__nv_bfloat162*)g_Wb)[i] = __floats2bfloat162_rn(v.x, v.y);
    }
}

// ---------------------------------------------------------------------------
// Kernel B: FUSED  GEMM (mma.sync bf16) + band/rows partials.
//   c[b,d,t] = sum_e W[d,e] * fc[b,e,t] + bias[d]  (kept in SMEM only)
//   band_p[q,b,k,s] = sum_{c in quarter} fe[b,c,s+k] * c[b,c,s]
//   rows_p[q,b,r,s] = sum_{c in quarter} fe[b,c,r]   * c[b,c,s]
// Block 128(m) x 128(n), BK=32, 256 threads.
// ---------------------------------------------------------------------------
#define BM 128
#define BN 128
#define BKT 32
#define APAD 40
#define BPAD 136
#define CPAD 136
#define FEW 144

#define AS_OFF 0
#define BS_OFF 10240
#define C_OFF  0
#define FE_OFF 34816
#define FER_OFF 39424
#define SMEM_BYTES 39936

__global__ __launch_bounds__(256) void fused_k(const float* __restrict__ fc,
                                               const float* __restrict__ fe,
                                               const float* __restrict__ bias) {
    __shared__ __align__(16) char smbuf[SMEM_BYTES];
    __nv_bfloat16* As = (__nv_bfloat16*)(smbuf + AS_OFF);
    __nv_bfloat16* Bs = (__nv_bfloat16*)(smbuf + BS_OFF);

    const int tid  = threadIdx.x;
    const int lane = tid & 31;
    const int wid  = tid >> 5;
    const int wm   = wid >> 2;          // 0..1
    const int wn   = wid & 3;           // 0..3

    const int b  = blockIdx.z;
    const int t0 = blockIdx.x * BN;
    const int d0 = blockIdx.y * BM;

    const uint32_t as_base = smem_u32(As);
    const uint32_t bs_base = smem_u32(Bs);

    const int grp = lane >> 3, lr = lane & 7;
    const uint32_t a_lane = (uint32_t)((wm * 64 + lr + (grp & 1) * 8) * APAD * 2
                                       + ((grp >> 1) * 8) * 2);
    const uint32_t b_lane = (uint32_t)(((grp & 1) * 8 + lr) * BPAD * 2
                                       + (wn * 32 + (grp >> 1) * 8) * 2);

    float acc[4][4][4];
#pragma unroll
    for (int i = 0; i < 4; i++)
#pragma unroll
        for (int j = 0; j < 4; j++)
#pragma unroll
            for (int q = 0; q < 4; q++) acc[i][j][q] = 0.f;

    const float* fcb = fc + (size_t)b * CH * TT;

    uint4  areg[2];
    float4 breg[4];

    // ---- prefetch tile 0
#pragma unroll
    for (int j = 0; j < 2; j++) {
        int seg = tid + j * 256;
        int row = seg >> 2, c8 = seg & 3;
        areg[j] = *(const uint4*)(g_Wb + (size_t)(d0 + row) * CH + c8 * 8);
    }
#pragma unroll
    for (int j = 0; j < 4; j++) {
        int seg = tid + j * 256;
        int row = seg >> 5, c4 = seg & 31;
        breg[j] = *(const float4*)(fcb + (size_t)row * TT + t0 + c4 * 4);
    }

    for (int kt = 0; kt < CH / BKT; kt++) {
        __syncthreads();
#pragma unroll
        for (int j = 0; j < 2; j++) {
            int seg = tid + j * 256;
            int row = seg >> 2, c8 = seg & 3;
            *(uint4*)(As + row * APAD + c8 * 8) = areg[j];
        }
#pragma unroll
        for (int j = 0; j < 4; j++) {
            int seg = tid + j * 256;
            int row = seg >> 5, c4 = seg & 31;
            float4 v = breg[j];
            __nv_bfloat162* p = (__nv_bfloat162*)(Bs + row * BPAD + c4 * 4);
            p[0] = __floats2bfloat162_rn(v.x, v.y);
            p[1] = __floats2bfloat162_rn(v.z, v.w);
        }
        __syncthreads();

        if (kt + 1 < CH / BKT) {
            const int k0 = (kt + 1) * BKT;
#pragma unroll
            for (int j = 0; j < 2; j++) {
                int seg = tid + j * 256;
                int row = seg >> 2, c8 = seg & 3;
                areg[j] = *(const uint4*)(g_Wb + (size_t)(d0 + row) * CH + k0 + c8 * 8);
            }
#pragma unroll
            for (int j = 0; j < 4; j++) {
                int seg = tid + j * 256;
                int row = seg >> 5, c4 = seg & 31;
                breg[j] = *(const float4*)(fcb + (size_t)(k0 + row) * TT + t0 + c4 * 4);
            }
        }

#pragma unroll
        for (int ks = 0; ks < 2; ks++) {
            uint32_t af[4][4];
#pragma unroll
            for (int fm = 0; fm < 4; fm++)
                ldsm_x4(af[fm], as_base + a_lane
                                + (uint32_t)(fm * 16 * APAD * 2 + ks * 16 * 2));
            uint32_t bf[2][4];
#pragma unroll
            for (int fn = 0; fn < 2; fn++)
                ldsm_x4_t(bf[fn], bs_base + b_lane
                                  + (uint32_t)(ks * 16 * BPAD * 2 + fn * 16 * 2));
#pragma unroll
            for (int fm = 0; fm < 4; fm++)
#pragma unroll
                for (int nf = 0; nf < 4; nf++)
                    mma16816(acc[fm][nf], af[fm], &bf[nf >> 1][(nf & 1) * 2]);
        }
    }

    // ================= epilogue 1: acc + bias -> c tile in SMEM (bf16) =====
    __syncthreads();      // done reading As/Bs; Cs overlaps them
    __nv_bfloat16* Cs = (__nv_bfloat16*)(smbuf + C_OFF);
    {
        const int rbase = lane >> 2;
        const int cbase = (lane & 3) * 2;
#pragma unroll
        for (int fm = 0; fm < 4; fm++) {
            const int dd = wm * 64 + fm * 16 + rbase;       // local channel
            const float bi_lo = bias[d0 + dd];
            const float bi_hi = bias[d0 + dd + 8];
#pragma unroll
            for (int nf = 0; nf < 4; nf++) {
                const int tt = wn * 32 + nf * 8 + cbase;
                *(__nv_bfloat162*)(Cs + dd * CPAD + tt) =
                    __floats2bfloat162_rn(acc[fm][nf][0] + bi_lo,
                                          acc[fm][nf][1] + bi_lo);
                *(__nv_bfloat162*)(Cs + (dd + 8) * CPAD + tt) =
                    __floats2bfloat162_rn(acc[fm][nf][2] + bi_hi,
                                          acc[fm][nf][3] + bi_hi);
            }
        }
    }
    __syncthreads();

    // ================= epilogue 2: band + rows partials ====================
    // thread owns 2 columns (t2, t2+1) and channel quarter h4 of each chunk
    __nv_bfloat162* FEs  = (__nv_bfloat162*)(smbuf + FE_OFF);   // [16][FEW/2]
    __nv_bfloat162* FERs = (__nv_bfloat162*)(smbuf + FER_OFF);  // [16][8]
    const int t2 = (tid & 63) * 2;
    const int h4 = tid >> 6;
    const float* feb = fe + (size_t)b * CH * TT;

    float accB[KS][2];
    float accR[NN][2];
#pragma unroll
    for (int k = 0; k < KS; k++) accB[k][0] = accB[k][1] = 0.f;
#pragma unroll
    for (int r = 0; r < NN; r++) accR[r][0] = accR[r][1] = 0.f;

    for (int cc = 0; cc < BM / 16; cc++) {
        const int chbase = d0 + cc * 16;
        // fe chunk: 16 channels x FEW cols (t0 .. t0+FEW-1), bf16, zero-padded
        for (int i = tid; i < 16 * (FEW / 2); i += 256) {
            int ch = i / (FEW / 2), jj = (i % (FEW / 2)) * 2;
            int col = t0 + jj;
            const float* row = feb + (size_t)(chbase + ch) * TT;
            float x0 = (col < TT)     ? row[col]     : 0.f;
            float x1 = (col + 1 < TT) ? row[col + 1] : 0.f;
            FEs[ch * (FEW / 2) + jj / 2] = __floats2bfloat162_rn(x0, x1);
        }
        // fer chunk: 16 channels x cols 0..9 (pad to 16)
        for (int i = tid; i < 16 * 16; i += 256) {
            int ch = i >> 4, r = i & 15;
            float v = (r < NN) ? feb[(size_t)(chbase + ch) * TT + r] : 0.f;
            ((__nv_bfloat16*)FERs)[ch * 16 + r] = __float2bfloat16(v);
        }
        __syncthreads();

#pragma unroll
        for (int j = 0; j < 4; j++) {
            const int lch = h4 * 4 + j;          // local channel in chunk (0..15)
            const int ch  = cc * 16 + lch;       // block-local channel (0..127), for Cs
            __nv_bfloat162 cv = *(__nv_bfloat162*)(Cs + ch * CPAD + t2);
            float c0 = __bfloat162float(cv.x);
            float c1 = __bfloat162float(cv.y);

            float w[14];
#pragma unroll
            for (int p = 0; p < 7; p++) {
                __nv_bfloat162 v = FEs[lch * (FEW / 2) + t2 / 2 + p];
                w[2 * p]     = __bfloat162float(v.x);
                w[2 * p + 1] = __bfloat162float(v.y);
            }
#pragma unroll
            for (int k = 0; k < KS; k++) {
                accB[k][0] += w[k] * c0;
                accB[k][1] += w[k + 1] * c1;
            }
#pragma unroll
            for (int p = 0; p < 5; p++) {
                __nv_bfloat162 v = FERs[lch * 8 + p];
                float f0 = __bfloat162float(v.x);
                float f1 = __bfloat162float(v.y);
                accR[2 * p][0]     += f0 * c0;
                accR[2 * p][1]     += f0 * c1;
                accR[2 * p + 1][0] += f1 * c0;
                accR[2 * p + 1][1] += f1 * c1;
            }
        }
        __syncthreads();
    }

    // write partials (q = m-block * 4 + channel quarter)
    const int q = blockIdx.y * 4 + h4;
#pragma unroll
    for (int k = 0; k < KS; k++) {
        float2 v = make_float2(accB[k][0], accB[k][1]);
        *(float2*)&g_band_p[((size_t)(q * BB + b) * KS + k) * TT + t0 + t2] = v;
    }
#pragma unroll
    for (int r = 0; r < NN; r++) {
        float2 v = make_float2(accR[r][0], accR[r][1]);
        *(float2*)&g_rows_p[((size_t)(q * BB + b) * NN + r) * TT + t0 + t2] = v;
    }
}

// ---------------------------------------------------------------------------
// Kernel C: combine partials (QS=16) + zero the total
// ---------------------------------------------------------------------------
__global__ void combine_k() {
    const int NB = BB * KS * TT;
    const int NR = BB * NN * TT;
    int i = blockIdx.x * blockDim.x + threadIdx.x;
    if (i == 0) g_total = 0.0;
    if (i < NB) {
        float v = 0.f;
#pragma unroll
        for (int q = 0; q < QS; q++) v += g_band_p[(size_t)q * NB + i];
        g_band[i] = v;
    } else if (i < NB + NR) {
        int j = i - NB;
        float v = 0.f;
#pragma unroll
        for (int q = 0; q < QS; q++) v += g_rows_p[(size_t)q * NR + j];
        g_rows[j] = v;
    }
}

// ---------------------------------------------------------------------------
// Kernel D: loss reduction (fp64 accumulation)
// ---------------------------------------------------------------------------
__device__ __forceinline__ float logsigf(float x) {
    float e = __expf(-fabsf(x));
    return fminf(x, 0.f) - __logf(1.f + e);
}

__global__ void loss_k(const int* __restrict__ neg_idx) {
    const int gid    = blockIdx.x * blockDim.x + threadIdx.x;
    const int stride = gridDim.x * blockDim.x;
    double local = 0.0;

    const int N1 = BB * KS * TT;
    for (int i = gid; i < N1; i += stride) {
        int s = i % TT;
        int k = (i / TT) % KS;
        if (s + k < TT) local += (double)logsigf(g_band[i]);
    }

    const int N2 = KS * BB * TT * NN;
    for (int i = gid; i < N2; i += stride) {
        int r  = i % NN;
        int s  = (i / NN) % TT;
        int bk = i / (NN * TT);
        int b  = bk % BB;
        int k  = bk / BB;
        int idx = neg_idx[(k * TT + s) * NN + r];
        float v = g_rows[((size_t)b * NN + r) * TT + idx];
        local += (double)NN * (double)logsigf(-v);
    }

#pragma unroll
    for (int off = 16; off; off >>= 1)
        local += __shfl_down_sync(0xffffffffu, local, off);
    __shared__ double warp_sums[32];
    int lane = threadIdx.x & 31, wid = threadIdx.x >> 5;
    if (lane == 0) warp_sums[wid] = local;
    __syncthreads();
    if (wid == 0) {
        int nw = blockDim.x >> 5;
        local = (lane < nw) ? warp_sums[lane] : 0.0;
#pragma unroll
        for (int off = 16; off; off >>= 1)
            local += __shfl_down_sync(0xffffffffu, local, off);
        if (lane == 0) atomicAdd(&g_total, local);
    }
}

__global__ void write_k(float* __restrict__ out) { out[0] = (float)g_total; }

// ---------------------------------------------------------------------------
// Launch
// ---------------------------------------------------------------------------
extern "C" void kernel_launch(void* const* d_in, const int* in_sizes, int n_in,
                              void* d_out, int out_size) {
    const float* fe   = (const float*)d_in[0];  // feat_enc     [B,C,T]
    const float* fc   = (const float*)d_in[1];  // feat_context [B,C,T]
    const float* W    = (const float*)d_in[2];  // [C,C]
    const float* bias = (const float*)d_in[3];  // [C]
    const int*   neg  = (const int*)d_in[4];    // [K_STEPS,T,NUM_NEG]

    convw_k<<<(CH * CH / 2 + 255) / 256, 256>>>(W);

    fused_k<<<dim3(TT / BN, CH / BM, BB), 256>>>(fc, fe, bias);

    const int NTOT = BB * (KS + NN) * TT;
    combine_k<<<(NTOT + 255) / 256, 256>>>();

    loss_k<<<1024, 256>>>(neg);
    write_k<<<1, 1>>>((float*)d_out);
}

// round 6
// speedup vs baseline: 4.7327x; 1.0060x over previous
#include <cuda_runtime.h>
#include <cuda_bf16.h>
#include <cstdint>

// Problem constants
#define CH 512
#define TT 4096
#define BB 2
#define KS 12
#define NN 10
#define QS 16          // 4 m-blocks x 4 in-block channel quarters

// ---------------------------------------------------------------------------
// Scratch (device globals; allocation is forbidden)
// ---------------------------------------------------------------------------
__device__ __nv_bfloat16 g_Wb[CH * CH];          // W in bf16, row-major [d][e]
__device__ float  g_band_p[QS * BB * KS * TT];   // 6.3 MB
__device__ float  g_rows_p[QS * BB * NN * TT];   // 5.2 MB
__device__ float  g_ls[BB * NN * TT];            // logsig(-rows)
__device__ double g_total;

// ---------------------------------------------------------------------------
// PTX helpers (baseline sm_80+: ldmatrix + mma.sync only)
// ---------------------------------------------------------------------------
__device__ __forceinline__ uint32_t smem_u32(const void* p) {
    uint32_t a;
    asm("{ .reg .u64 t; cvta.to.shared.u64 t, %1; cvt.u32.u64 %0, t; }"
        : "=r"(a) : "l"(p));
    return a;
}
__device__ __forceinline__ void ldsm_x4(uint32_t* r, uint32_t addr) {
    asm volatile("ldmatrix.sync.aligned.m8n8.x4.shared.b16 {%0,%1,%2,%3}, [%4];"
                 : "=r"(r[0]), "=r"(r[1]), "=r"(r[2]), "=r"(r[3]) : "r"(addr));
}
__device__ __forceinline__ void ldsm_x4_t(uint32_t* r, uint32_t addr) {
    asm volatile("ldmatrix.sync.aligned.m8n8.x4.trans.shared.b16 {%0,%1,%2,%3}, [%4];"
                 : "=r"(r[0]), "=r"(r[1]), "=r"(r[2]), "=r"(r[3]) : "r"(addr));
}
__device__ __forceinline__ void mma16816(float* d, const uint32_t* a,
                                         const uint32_t* b) {
    asm volatile(
        "mma.sync.aligned.m16n8k16.row.col.f32.bf16.bf16.f32 "
        "{%0,%1,%2,%3}, {%4,%5,%6,%7}, {%8,%9}, {%0,%1,%2,%3};"
        : "+f"(d[0]), "+f"(d[1]), "+f"(d[2]), "+f"(d[3])
        : "r"(a[0]), "r"(a[1]), "r"(a[2]), "r"(a[3]), "r"(b[0]), "r"(b[1]));
}

__device__ __forceinline__ float logsigf(float x) {
    float e = __expf(-fabsf(x));
    return fminf(x, 0.f) - __logf(1.f + e);
}

// ---------------------------------------------------------------------------
// Kernel A: convert W to bf16, zero the total
// ---------------------------------------------------------------------------
__global__ void convw_k(const float* __restrict__ W) {
    int i = blockIdx.x * blockDim.x + threadIdx.x;   // over float2
    if (i == 0) g_total = 0.0;
    if (i < CH * CH / 2) {
        float2 v = ((const float2*)W)[i];
        ((__nv_bfloat162*)g_Wb)[i] = __floats2bfloat162_rn(v.x, v.y);
    }
}

// ---------------------------------------------------------------------------
// Kernel B: FUSED  GEMM (mma.sync bf16) + band/rows partials.
//   c[b,d,t] = sum_e W[d,e] * fc[b,e,t] + bias[d]  (kept in SMEM only)
//   band_p[q,b,k,s] = sum_{c in quarter} fe[b,c,s+k] * c[b,c,s]
//   rows_p[q,b,r,s] = sum_{c in quarter} fe[b,c,r]   * c[b,c,s]
// Block 128(m) x 128(n), BK=32, 256 threads, forced 2 CTAs/SM.
// ---------------------------------------------------------------------------
#define BM 128
#define BN 128
#define BKT 32
#define APAD 40
#define BPAD 136
#define CPAD 136
#define FEW 144

#define AS_OFF 0
#define BS_OFF 10240
#define C_OFF  0
#define FE_OFF 34816
#define FER_OFF 39424
#define SMEM_BYTES 39936

__global__ __launch_bounds__(256, 2) void fused_k(const float* __restrict__ fc,
                                                  const float* __restrict__ fe,
                                                  const float* __restrict__ bias) {
    __shared__ __align__(16) char smbuf[SMEM_BYTES];
    __nv_bfloat16* As = (__nv_bfloat16*)(smbuf + AS_OFF);
    __nv_bfloat16* Bs = (__nv_bfloat16*)(smbuf + BS_OFF);

    const int tid  = threadIdx.x;
    const int lane = tid & 31;
    const int wid  = tid >> 5;
    const int wm   = wid >> 2;          // 0..1
    const int wn   = wid & 3;           // 0..3

    const int b  = blockIdx.z;
    const int t0 = blockIdx.x * BN;
    const int d0 = blockIdx.y * BM;

    const uint32_t as_base = smem_u32(As);
    const uint32_t bs_base = smem_u32(Bs);

    const int grp = lane >> 3, lr = lane & 7;
    const uint32_t a_lane = (uint32_t)((wm * 64 + lr + (grp & 1) * 8) * APAD * 2
                                       + ((grp >> 1) * 8) * 2);
    const uint32_t b_lane = (uint32_t)(((grp & 1) * 8 + lr) * BPAD * 2
                                       + (wn * 32 + (grp >> 1) * 8) * 2);

    float acc[4][4][4];
#pragma unroll
    for (int i = 0; i < 4; i++)
#pragma unroll
        for (int j = 0; j < 4; j++)
#pragma unroll
            for (int q = 0; q < 4; q++) acc[i][j][q] = 0.f;

    const float* fcb = fc + (size_t)b * CH * TT;

    uint4  areg[2];
    float4 breg[4];

    // ---- prefetch tile 0
#pragma unroll
    for (int j = 0; j < 2; j++) {
        int seg = tid + j * 256;
        int row = seg >> 2, c8 = seg & 3;
        areg[j] = *(const uint4*)(g_Wb + (size_t)(d0 + row) * CH + c8 * 8);
    }
#pragma unroll
    for (int j = 0; j < 4; j++) {
        int seg = tid + j * 256;
        int row = seg >> 5, c4 = seg & 31;
        breg[j] = *(const float4*)(fcb + (size_t)row * TT + t0 + c4 * 4);
    }

    for (int kt = 0; kt < CH / BKT; kt++) {
        __syncthreads();
#pragma unroll
        for (int j = 0; j < 2; j++) {
            int seg = tid + j * 256;
            int row = seg >> 2, c8 = seg & 3;
            *(uint4*)(As + row * APAD + c8 * 8) = areg[j];
        }
#pragma unroll
        for (int j = 0; j < 4; j++) {
            int seg = tid + j * 256;
            int row = seg >> 5, c4 = seg & 31;
            float4 v = breg[j];
            __nv_bfloat162* p = (__nv_bfloat162*)(Bs + row * BPAD + c4 * 4);
            p[0] = __floats2bfloat162_rn(v.x, v.y);
            p[1] = __floats2bfloat162_rn(v.z, v.w);
        }
        __syncthreads();

        if (kt + 1 < CH / BKT) {
            const int k0 = (kt + 1) * BKT;
#pragma unroll
            for (int j = 0; j < 2; j++) {
                int seg = tid + j * 256;
                int row = seg >> 2, c8 = seg & 3;
                areg[j] = *(const uint4*)(g_Wb + (size_t)(d0 + row) * CH + k0 + c8 * 8);
            }
#pragma unroll
            for (int j = 0; j < 4; j++) {
                int seg = tid + j * 256;
                int row = seg >> 5, c4 = seg & 31;
                breg[j] = *(const float4*)(fcb + (size_t)(k0 + row) * TT + t0 + c4 * 4);
            }
        }

#pragma unroll
        for (int ks = 0; ks < 2; ks++) {
            uint32_t af[4][4];
#pragma unroll
            for (int fm = 0; fm < 4; fm++)
                ldsm_x4(af[fm], as_base + a_lane
                                + (uint32_t)(fm * 16 * APAD * 2 + ks * 16 * 2));
            uint32_t bf[2][4];
#pragma unroll
            for (int fn = 0; fn < 2; fn++)
                ldsm_x4_t(bf[fn], bs_base + b_lane
                                  + (uint32_t)(ks * 16 * BPAD * 2 + fn * 16 * 2));
#pragma unroll
            for (int fm = 0; fm < 4; fm++)
#pragma unroll
                for (int nf = 0; nf < 4; nf++)
                    mma16816(acc[fm][nf], af[fm], &bf[nf >> 1][(nf & 1) * 2]);
        }
    }

    // ================= epilogue 1: acc + bias -> c tile in SMEM (bf16) =====
    __syncthreads();      // done reading As/Bs; Cs overlaps them
    __nv_bfloat16* Cs = (__nv_bfloat16*)(smbuf + C_OFF);
    {
        const int rbase = lane >> 2;
        const int cbase = (lane & 3) * 2;
#pragma unroll
        for (int fm = 0; fm < 4; fm++) {
            const int dd = wm * 64 + fm * 16 + rbase;       // local channel
            const float bi_lo = bias[d0 + dd];
            const float bi_hi = bias[d0 + dd + 8];
#pragma unroll
            for (int nf = 0; nf < 4; nf++) {
                const int tt = wn * 32 + nf * 8 + cbase;
                *(__nv_bfloat162*)(Cs + dd * CPAD + tt) =
                    __floats2bfloat162_rn(acc[fm][nf][0] + bi_lo,
                                          acc[fm][nf][1] + bi_lo);
                *(__nv_bfloat162*)(Cs + (dd + 8) * CPAD + tt) =
                    __floats2bfloat162_rn(acc[fm][nf][2] + bi_hi,
                                          acc[fm][nf][3] + bi_hi);
            }
        }
    }
    __syncthreads();

    // ================= epilogue 2: band + rows partials ====================
    __nv_bfloat162* FEs  = (__nv_bfloat162*)(smbuf + FE_OFF);   // [16][FEW/2]
    __nv_bfloat162* FERs = (__nv_bfloat162*)(smbuf + FER_OFF);  // [16][8]
    const int t2 = (tid & 63) * 2;
    const int h4 = tid >> 6;
    const float* feb = fe + (size_t)b * CH * TT;

    float accB[KS][2];
    float accR[NN][2];
#pragma unroll
    for (int k = 0; k < KS; k++) accB[k][0] = accB[k][1] = 0.f;
#pragma unroll
    for (int r = 0; r < NN; r++) accR[r][0] = accR[r][1] = 0.f;

    for (int cc = 0; cc < BM / 16; cc++) {
        const int chbase = d0 + cc * 16;
        for (int i = tid; i < 16 * (FEW / 2); i += 256) {
            int ch = i / (FEW / 2), jj = (i % (FEW / 2)) * 2;
            int col = t0 + jj;
            const float* row = feb + (size_t)(chbase + ch) * TT;
            float x0 = (col < TT)     ? row[col]     : 0.f;
            float x1 = (col + 1 < TT) ? row[col + 1] : 0.f;
            FEs[ch * (FEW / 2) + jj / 2] = __floats2bfloat162_rn(x0, x1);
        }
        for (int i = tid; i < 16 * 16; i += 256) {
            int ch = i >> 4, r = i & 15;
            float v = (r < NN) ? feb[(size_t)(chbase + ch) * TT + r] : 0.f;
            ((__nv_bfloat16*)FERs)[ch * 16 + r] = __float2bfloat16(v);
        }
        __syncthreads();

#pragma unroll
        for (int j = 0; j < 4; j++) {
            const int lch = h4 * 4 + j;          // local channel in chunk (0..15)
            const int ch  = cc * 16 + lch;       // block-local channel, for Cs
            __nv_bfloat162 cv = *(__nv_bfloat162*)(Cs + ch * CPAD + t2);
            float c0 = __bfloat162float(cv.x);
            float c1 = __bfloat162float(cv.y);

            float w[14];
#pragma unroll
            for (int p = 0; p < 7; p++) {
                __nv_bfloat162 v = FEs[lch * (FEW / 2) + t2 / 2 + p];
                w[2 * p]     = __bfloat162float(v.x);
                w[2 * p + 1] = __bfloat162float(v.y);
            }
#pragma unroll
            for (int k = 0; k < KS; k++) {
                accB[k][0] += w[k] * c0;
                accB[k][1] += w[k + 1] * c1;
            }
#pragma unroll
            for (int p = 0; p < 5; p++) {
                __nv_bfloat162 v = FERs[lch * 8 + p];
                float f0 = __bfloat162float(v.x);
                float f1 = __bfloat162float(v.y);
                accR[2 * p][0]     += f0 * c0;
                accR[2 * p][1]     += f0 * c1;
                accR[2 * p + 1][0] += f1 * c0;
                accR[2 * p + 1][1] += f1 * c1;
            }
        }
        __syncthreads();
    }

    // write partials (q = m-block * 4 + channel quarter)
    const int q = blockIdx.y * 4 + h4;
#pragma unroll
    for (int k = 0; k < KS; k++) {
        float2 v = make_float2(accB[k][0], accB[k][1]);
        *(float2*)&g_band_p[((size_t)(q * BB + b) * KS + k) * TT + t0 + t2] = v;
    }
#pragma unroll
    for (int r = 0; r < NN; r++) {
        float2 v = make_float2(accR[r][0], accR[r][1]);
        *(float2*)&g_rows_p[((size_t)(q * BB + b) * NN + r) * TT + t0 + t2] = v;
    }
}

// ---------------------------------------------------------------------------
// Kernel C: combine partials + positives loss + ls table
//   band elems: sum partials, apply mask, accumulate logsig into g_total.
//   rows elems: sum partials, store logsig(-v) into g_ls.
// ---------------------------------------------------------------------------
__global__ __launch_bounds__(256) void combine_k() {
    const int NB = BB * KS * TT;
    const int NR = BB * NN * TT;
    int i = blockIdx.x * blockDim.x + threadIdx.x;
    double local = 0.0;
    if (i < NB) {
        float v = 0.f;
#pragma unroll
        for (int q = 0; q < QS; q++) v += g_band_p[(size_t)q * NB + i];
        int s = i % TT;
        int k = (i / TT) % KS;
        if (s + k < TT) local = (double)logsigf(v);
    } else if (i < NB + NR) {
        int j = i - NB;
        float v = 0.f;
#pragma unroll
        for (int q = 0; q < QS; q++) v += g_rows_p[(size_t)q * NR + j];
        g_ls[j] = logsigf(-v);
    }
    // block reduce the positive contributions
#pragma unroll
    for (int off = 16; off; off >>= 1)
        local += __shfl_down_sync(0xffffffffu, local, off);
    __shared__ double warp_sums[8];
    int lane = threadIdx.x & 31, wid = threadIdx.x >> 5;
    if (lane == 0) warp_sums[wid] = local;
    __syncthreads();
    if (wid == 0) {
        local = (lane < 8) ? warp_sums[lane] : 0.0;
#pragma unroll
        for (int off = 4; off; off >>= 1)
            local += __shfl_down_sync(0xffffffffu, local, off);
        if (lane == 0 && local != 0.0) atomicAdd(&g_total, local);
    }
}

// ---------------------------------------------------------------------------
// Kernel D: negatives — gather-sum of ls table, 8 gathers in flight/thread
//   total += NN * sum ls[b, r, neg_idx[k,s,r]]
// ---------------------------------------------------------------------------
#define LGRID 480
#define LBATCH 8

__global__ __launch_bounds__(256) void loss_k(const int* __restrict__ neg_idx) {
    const int gid    = blockIdx.x * 256 + threadIdx.x;
    const int stride = LGRID * 256;            // 122880
    // N2 = KS*BB*TT*NN = 983040 = stride * 8 exactly
    float vs[LBATCH];
#pragma unroll
    for (int j = 0; j < LBATCH; j++) {
        int i  = gid + j * stride;
        int r  = i % NN;
        int s  = (i / NN) % TT;
        int bk = i / (NN * TT);
        int b  = bk % BB;
        int k  = bk / BB;
        int idx = __ldg(&neg_idx[(k * TT + s) * NN + r]);
        vs[j] = g_ls[((size_t)b * NN + r) * TT + idx];
    }
    float fsum = 0.f;
#pragma unroll
    for (int j = 0; j < LBATCH; j++) fsum += vs[j];
    double local = (double)NN * (double)fsum;

#pragma unroll
    for (int off = 16; off; off >>= 1)
        local += __shfl_down_sync(0xffffffffu, local, off);
    __shared__ double warp_sums[8];
    int lane = threadIdx.x & 31, wid = threadIdx.x >> 5;
    if (lane == 0) warp_sums[wid] = local;
    __syncthreads();
    if (wid == 0) {
        local = (lane < 8) ? warp_sums[lane] : 0.0;
#pragma unroll
        for (int off = 4; off; off >>= 1)
            local += __shfl_down_sync(0xffffffffu, local, off);
        if (lane == 0) atomicAdd(&g_total, local);
    }
}

__global__ void write_k(float* __restrict__ out) { out[0] = (float)g_total; }

// ---------------------------------------------------------------------------
// Launch
// ---------------------------------------------------------------------------
extern "C" void kernel_launch(void* const* d_in, const int* in_sizes, int n_in,
                              void* d_out, int out_size) {
    const float* fe   = (const float*)d_in[0];  // feat_enc     [B,C,T]
    const float* fc   = (const float*)d_in[1];  // feat_context [B,C,T]
    const float* W    = (const float*)d_in[2];  // [C,C]
    const float* bias = (const float*)d_in[3];  // [C]
    const int*   neg  = (const int*)d_in[4];    // [K_STEPS,T,NUM_NEG]

    convw_k<<<(CH * CH / 2 + 255) / 256, 256>>>(W);

    fused_k<<<dim3(TT / BN, CH / BM, BB), 256>>>(fc, fe, bias);

    const int NTOT = BB * (KS + NN) * TT;
    combine_k<<<(NTOT + 255) / 256, 256>>>();

    loss_k<<<LGRID, 256>>>(neg);
    write_k<<<1, 1>>>((float*)d_out);
}